// round 16
// baseline (speedup 1.0000x reference)
#include <cuda_runtime.h>
#include <cuda_bf16.h>
#include <cuda_fp16.h>
#include <math.h>
#include <stdint.h>

// Model dims
#define LNUM 12
#define DMODEL 768
#define NHEAD 6
#define HDIM 128
#define FFDIM 3072
#define VOCAB 65536
#define SEQ 2048
#define EPSV 1e-5f
#define CAPV 30.0f

#define K2D (2 * DMODEL)   // 1536: 2-plane row stride for K=768 operands
#define K2F (2 * FFDIM)    // 6144: 2-plane row stride for K=3072 operand

// GEMM tiling: 128x128 tile, BK=64 (true K), 3-stage, fused 3-mma planes
#define LDS 72
#define TB (128 * LDS * 2)          // 18432 B per 128x64 fp16 tile (padded)
#define G4_SMEM (3 * 4 * TB)        // 221184 B (Ah,Al,Bh,Bl x 3 stages)
#define G3_SMEM (3 * 3 * TB)        // 165888 B (Ah,Bh,Bl x 3 stages) lm_head
// attention dynamic smem: Ktf[32][35] + Vtf[32][32] + sq4[32][32] (float4)
#define ATTN_SMEM ((32 * 35 + 32 * 32 + 32 * 32) * 16)

// ---------------- scratch (static device arrays; no allocation) -------------
__device__ float g_x[SEQ * DMODEL];
__device__ float g_big[SEQ * 3 * DMODEL];
__device__ float g_q[SEQ * DMODEL];
__device__ float g_k[SEQ * DMODEL];
__device__ float g_v[SEQ * DMODEL];
__device__ float g_rowsum[SEQ];
__device__ float g_tl[SEQ];

// 2-plane fp16 split weights: row n = [hi(0..K) | lo(K..2K)]
__device__ __align__(16) __half w2_qkv[12LL * 2304 * K2D];
__device__ __align__(16) __half w2_proj[12LL * 768 * K2D];
__device__ __align__(16) __half w2_fc1[12LL * 3072 * K2D];
__device__ __align__(16) __half w2_fc2[12LL * 768 * K2F];
__device__ __align__(16) __half w2_lm[65536LL * K2D];

// 2-plane activations
__device__ __align__(16) __half an2[SEQ * K2D];
__device__ __align__(16) __half ah2[SEQ * K2F];

// ---------------- helpers ----------------------------------------------------
__device__ __forceinline__ void split2h(float v, __half& h, __half& l) {
    h = __float2half_rn(v);
    l = __float2half_rn(v - __half2float(h));
}

__device__ __forceinline__ float blockReduceSum(float v) {
    __shared__ float sh[32];
    __syncthreads();
    int lane = threadIdx.x & 31, wid = threadIdx.x >> 5;
    #pragma unroll
    for (int o = 16; o; o >>= 1) v += __shfl_xor_sync(0xffffffffu, v, o);
    if (lane == 0) sh[wid] = v;
    __syncthreads();
    int nw = blockDim.x >> 5;
    v = (threadIdx.x < nw) ? sh[threadIdx.x] : 0.f;
    if (wid == 0) {
        #pragma unroll
        for (int o = 16; o; o >>= 1) v += __shfl_xor_sync(0xffffffffu, v, o);
        if (lane == 0) sh[0] = v;
    }
    __syncthreads();
    return sh[0];
}

__device__ __forceinline__ void ldsm4(uint32_t (&r)[4], uint32_t addr) {
    asm volatile("ldmatrix.sync.aligned.m8n8.x4.shared.b16 {%0,%1,%2,%3},[%4];"
                 : "=r"(r[0]), "=r"(r[1]), "=r"(r[2]), "=r"(r[3]) : "r"(addr));
}

__device__ __forceinline__ void mma_f32acc(float (&d)[4], const uint32_t (&a)[4],
                                           uint32_t b0, uint32_t b1) {
    asm volatile(
        "mma.sync.aligned.m16n8k16.row.col.f32.f16.f16.f32 "
        "{%0,%1,%2,%3},{%4,%5,%6,%7},{%8,%9},{%0,%1,%2,%3};"
        : "+f"(d[0]), "+f"(d[1]), "+f"(d[2]), "+f"(d[3])
        : "r"(a[0]), "r"(a[1]), "r"(a[2]), "r"(a[3]), "r"(b0), "r"(b1));
}

__device__ __forceinline__ void cp16(uint32_t dst, const void* src) {
    asm volatile("cp.async.cg.shared.global [%0], [%1], 16;" :: "r"(dst), "l"(src));
}
#define CP_COMMIT() asm volatile("cp.async.commit_group;")
#define CP_WAIT1() asm volatile("cp.async.wait_group 1;")

// load one 4-tile stage: Ah,Al (from A 2-plane) + Bh,Bl (from B 2-plane).
// gA/gB point at the hi-plane column of this K-chunk. 16 cp16/thread.
__device__ __forceinline__ void load4(uint32_t s, const __half* gA,
                                      const __half* gB, int K, int tid) {
    int r = tid >> 1, c0 = (tid & 1) * 32;
    const __half* a = gA + (size_t)r * (2 * (size_t)K);
    const __half* b = gB + (size_t)r * (2 * (size_t)K);
    uint32_t so = (uint32_t)(r * LDS + c0) * 2;
    #pragma unroll
    for (int c = 0; c < 4; c++) {
        cp16(s + so + c * 16, a + c0 + c * 8);                 // Ah
        cp16(s + TB + so + c * 16, a + K + c0 + c * 8);        // Al
        cp16(s + 2 * TB + so + c * 16, b + c0 + c * 8);        // Bh
        cp16(s + 3 * TB + so + c * 16, b + K + c0 + c * 8);    // Bl
    }
}

// 3-tile stage for lm_head: Ah + Bh,Bl. 12 cp16/thread.
__device__ __forceinline__ void load3(uint32_t s, const __half* gA,
                                      const __half* gB, int K, int tid) {
    int r = tid >> 1, c0 = (tid & 1) * 32;
    const __half* a = gA + (size_t)r * (2 * (size_t)K);
    const __half* b = gB + (size_t)r * (2 * (size_t)K);
    uint32_t so = (uint32_t)(r * LDS + c0) * 2;
    #pragma unroll
    for (int c = 0; c < 4; c++) {
        cp16(s + so + c * 16, a + c0 + c * 8);                 // Ah
        cp16(s + TB + so + c * 16, b + c0 + c * 8);            // Bh
        cp16(s + 2 * TB + so + c * 16, b + K + c0 + c * 8);    // Bl
    }
}

// ---------------- fused weight split: ONE launch, 2-plane [hi|lo] -------------
__device__ __forceinline__ void split_seg2(const float4* s, __half* d,
                                           unsigned n4, unsigned K,
                                           unsigned gid, unsigned gstride) {
    unsigned K4 = K >> 2;
    for (unsigned i = gid; i < n4; i += gstride) {
        float4 v = s[i];
        unsigned n = i / K4;
        unsigned k = (i - n * K4) << 2;
        __half* r = d + (size_t)n * 2 * K + k;
        float vv[4] = {v.x, v.y, v.z, v.w};
        #pragma unroll
        for (int j = 0; j < 4; j++) {
            __half h, l;
            split2h(vv[j], h, l);
            r[j] = h; r[K + j] = l;
        }
    }
}

__global__ void split_all_kernel(const float4* qkv, const float4* proj,
                                 const float4* fc1, const float4* fc2,
                                 const float4* lm,
                                 __half* dqkv, __half* dproj,
                                 __half* dfc1, __half* dfc2, __half* dlm) {
    unsigned gid = blockIdx.x * blockDim.x + threadIdx.x;
    unsigned gs = gridDim.x * blockDim.x;
    split_seg2(qkv, dqkv, 12u * 2304 * 768 / 4, DMODEL, gid, gs);
    split_seg2(proj, dproj, 12u * 768 * 768 / 4, DMODEL, gid, gs);
    split_seg2(fc1, dfc1, 12u * 3072 * 768 / 4, DMODEL, gid, gs);
    split_seg2(fc2, dfc2, 12u * 768 * 3072 / 4, FFDIM, gid, gs);
    split_seg2(lm, dlm, 65536u * 768 / 4, DMODEL, gid, gs);
}

// ---------------- elementwise kernels ----------------------------------------
__global__ void embed_kernel(const int* __restrict__ idx,
                             const float* __restrict__ emb) {
    int t = blockIdx.x;
    int row = idx[t];
    const float* src = emb + (size_t)row * DMODEL;
    for (int i = threadIdx.x; i < DMODEL; i += blockDim.x)
        g_x[t * DMODEL + i] = src[i];
}

__global__ void rmsnorm_kernel(const float* __restrict__ x,
                               const float* __restrict__ w) {
    int t = blockIdx.x;
    const float* xr = x + (size_t)t * DMODEL;
    float s = 0.f;
    for (int i = threadIdx.x; i < DMODEL; i += blockDim.x) {
        float v = xr[i];
        s += v * v;
    }
    s = blockReduceSum(s);
    float r = rsqrtf(s / (float)DMODEL + EPSV);
    for (int i = threadIdx.x; i < DMODEL; i += blockDim.x) {
        float v = xr[i] * r * w[i];
        __half h, l;
        split2h(v, h, l);
        size_t o = (size_t)t * K2D + i;
        an2[o] = h; an2[o + DMODEL] = l;
    }
}

__global__ void rope_kernel(const float* __restrict__ qkv,
                            const float* __restrict__ qw,
                            const float* __restrict__ kw) {
    int t = blockIdx.x, h = blockIdx.y, d = threadIdx.x;
    const float* base = qkv + (size_t)t * (3 * DMODEL);
    float qd = base[h * HDIM + d];
    float kd = base[DMODEL + h * HDIM + d];
    float vd = base[2 * DMODEL + h * HDIM + d];
    float qs = blockReduceSum(qd * qd);
    float ks = blockReduceSum(kd * kd);
    float qn = qd * rsqrtf(qs / (float)HDIM + EPSV) * qw[d];
    float kn = kd * rsqrtf(ks / (float)HDIM + EPSV) * kw[d];
    __shared__ float sq[HDIM], sk[HDIM];
    sq[d] = qn; sk[d] = kn;
    __syncthreads();
    float expo = -(float)((d & 63) * 2) / (float)HDIM;
    float invf = expf(expo * logf(10000.f));
    float ang = (float)t * invf;
    float c = cosf(ang), s = sinf(ang);
    float qr = (d < 64) ? -sq[d + 64] : sq[d - 64];
    float kr = (d < 64) ? -sk[d + 64] : sk[d - 64];
    size_t oidx = (size_t)t * DMODEL + h * HDIM + d;
    g_q[oidx] = qn * c + qr * s;
    g_k[oidx] = kn * c + kr * s;
    g_v[oidx] = vd;
}

// ---------------- attention: 4 queries per warp, tile-wise online softmax ----
__global__ void __launch_bounds__(256) attn_kernel() {
    extern __shared__ float4 dyn[];
    float4 (*Ktf)[35] = (float4(*)[35])dyn;
    float4 (*Vtf)[32] = (float4(*)[32])(dyn + 32 * 35);
    float4 (*sq4)[32] = (float4(*)[32])(dyn + 32 * 35 + 32 * 32);
    const int h = blockIdx.y;
    const int qbase = blockIdx.x * 32;
    const int tid = threadIdx.x;
    const int warp = tid >> 5, lane = tid & 31;
    const int q0i = qbase + warp * 4;

    #pragma unroll
    for (int it = 0; it < 4; it++) {
        int i = tid + it * 256;
        int r = i >> 5, c4 = i & 31;
        sq4[r][c4] = ((const float4*)(g_q + (size_t)(qbase + r) * DMODEL +
                                      h * HDIM))[c4];
    }

    float m[4], l[4];
    float4 acc[4];
    #pragma unroll
    for (int qq = 0; qq < 4; qq++) {
        m[qq] = -1e30f; l[qq] = 0.f;
        acc[qq] = make_float4(0.f, 0.f, 0.f, 0.f);
    }
    const int ntiles = (qbase >> 5) + 1;

    for (int tb = 0; tb < ntiles; tb++) {
        int kb = tb << 5;
        __syncthreads();
        #pragma unroll
        for (int it = 0; it < 4; it++) {
            int i = tid + it * 256;
            int r = i >> 5, c4 = i & 31;
            Ktf[c4][r] = ((const float4*)(g_k + (size_t)(kb + r) * DMODEL +
                                          h * HDIM))[c4];
            Vtf[r][c4] = ((const float4*)(g_v + (size_t)(kb + r) * DMODEL +
                                          h * HDIM))[c4];
        }
        __syncthreads();

        float s[4] = {0.f, 0.f, 0.f, 0.f};
        #pragma unroll
        for (int d4 = 0; d4 < 32; d4 += 4) {
            float4 k0 = Ktf[d4][lane],     k1 = Ktf[d4 + 1][lane];
            float4 k2 = Ktf[d4 + 2][lane], k3 = Ktf[d4 + 3][lane];
            #pragma unroll
            for (int qq = 0; qq < 4; qq++) {
                float4 q0 = sq4[warp * 4 + qq][d4];
                float4 q1 = sq4[warp * 4 + qq][d4 + 1];
                float4 q2 = sq4[warp * 4 + qq][d4 + 2];
                float4 q3 = sq4[warp * 4 + qq][d4 + 3];
                s[qq] += q0.x * k0.x + q0.y * k0.y + q0.z * k0.z + q0.w * k0.w
                       + q1.x * k1.x + q1.y * k1.y + q1.z * k1.z + q1.w * k1.w
                       + q2.x * k2.x + q2.y * k2.y + q2.z * k2.z + q2.w * k2.w
                       + q3.x * k3.x + q3.y * k3.y + q3.z * k3.z + q3.w * k3.w;
            }
        }
        float p4[4];
        #pragma unroll
        for (int qq = 0; qq < 4; qq++) {
            int jmax = q0i + qq - kb + 1;
            float sv = s[qq] * 0.08838834764831845f;
            if (lane >= jmax) sv = -1e30f;
            float mt = sv;
            #pragma unroll
            for (int o = 16; o; o >>= 1)
                mt = fmaxf(mt, __shfl_xor_sync(0xffffffffu, mt, o));
            float mn = fmaxf(m[qq], mt);
            float corr = __expf(m[qq] - mn);
            float p = __expf(sv - mn);
            float psum = p;
            #pragma unroll
            for (int o = 16; o; o >>= 1)
                psum += __shfl_xor_sync(0xffffffffu, psum, o);
            l[qq] = l[qq] * corr + psum;
            m[qq] = mn;
            acc[qq].x *= corr; acc[qq].y *= corr;
            acc[qq].z *= corr; acc[qq].w *= corr;
            p4[qq] = p;
        }
        #pragma unroll
        for (int j = 0; j < 32; j++) {
            float4 vv = Vtf[j][lane];
            #pragma unroll
            for (int qq = 0; qq < 4; qq++) {
                float pj = __shfl_sync(0xffffffffu, p4[qq], j);
                acc[qq].x += pj * vv.x; acc[qq].y += pj * vv.y;
                acc[qq].z += pj * vv.z; acc[qq].w += pj * vv.w;
            }
        }
    }
    #pragma unroll
    for (int qq = 0; qq < 4; qq++) {
        float inv = 1.f / l[qq];
        float ov[4] = {acc[qq].x * inv, acc[qq].y * inv,
                       acc[qq].z * inv, acc[qq].w * inv};
        #pragma unroll
        for (int q = 0; q < 4; q++) {
            int i = h * HDIM + lane * 4 + q;
            __half hh, ll;
            split2h(ov[q], hh, ll);
            size_t o = (size_t)(q0i + qq) * K2D + i;
            an2[o] = hh; an2[o + DMODEL] = ll;
        }
    }
}

// ---------------- fused 3-mma GEMM 128x128: C = A * B^T (2-plane operands) ---
// Per K-chunk: load {Ah,Al,Bh,Bl}; acc += Ah*Bh + Ah*Bl + Al*Bh.
// epi: 0 = f32 store, 1 = +res f32 store, 2 = relu^2 -> 2-plane fp16 O2,
//      3 = atomicAdd into C (split-K; blockIdx.z selects K chunk)
__global__ void __launch_bounds__(256, 1)
gemm2_kernel(const __half* __restrict__ A, const __half* __restrict__ B,
             float* __restrict__ C, const float* __restrict__ res,
             __half* __restrict__ O2,
             int M, int N, int K, int epi, int ksplit) {
    extern __shared__ __half smem[];
    const int tid = threadIdx.x, lane = tid & 31, wid = tid >> 5;
    const int wm = wid >> 2, wn = wid & 3;
    const int m0 = blockIdx.x * 128, n0 = blockIdx.y * 128;
    const uint32_t sb = (uint32_t)__cvta_generic_to_shared(smem);
    const int nk = K / 64 / ksplit;
    const int koff = blockIdx.z * nk * 64;
    const __half* gA = A + (size_t)m0 * 2 * K + koff;
    const __half* gB = B + (size_t)n0 * 2 * K + koff;

    float acc[4][4][4];
    #pragma unroll
    for (int a = 0; a < 4; a++)
        #pragma unroll
        for (int b = 0; b < 4; b++)
            #pragma unroll
            for (int c = 0; c < 4; c++) acc[a][b][c] = 0.f;

    load4(sb, gA, gB, K, tid);
    CP_COMMIT();
    load4(sb + 4 * TB, gA + 64, gB + 64, K, tid);
    CP_COMMIT();

    for (int k = 0; k < nk; k++) {
        CP_WAIT1();
        __syncthreads();
        uint32_t st = sb + (uint32_t)(k % 3) * (4 * TB);
        uint32_t aH = st, aL = st + TB, bH = st + 2 * TB, bL = st + 3 * TB;
        #pragma unroll
        for (int kh = 0; kh < 4; kh++) {
            const int acol = kh * 16 + ((lane >> 4) << 3);
            const int bcol = kh * 16 + (((lane >> 3) & 1) << 3);
            const int brow = wn * 32 + ((lane >> 4) << 3) + (lane & 7);
            uint32_t a_h[4][4], b_h[2][4];
            #pragma unroll
            for (int mt = 0; mt < 4; mt++) {
                int arow = wm * 64 + mt * 16 + (lane & 15);
                ldsm4(a_h[mt], aH + (uint32_t)(arow * LDS + acol) * 2);
            }
            #pragma unroll
            for (int p = 0; p < 2; p++)
                ldsm4(b_h[p], bH + (uint32_t)((brow + p * 16) * LDS + bcol) * 2);
            #pragma unroll
            for (int mt = 0; mt < 4; mt++)
                #pragma unroll
                for (int nt = 0; nt < 4; nt++)
                    mma_f32acc(acc[mt][nt], a_h[mt], b_h[nt >> 1][(nt & 1) * 2],
                               b_h[nt >> 1][(nt & 1) * 2 + 1]);
            uint32_t b_l[2][4];
            #pragma unroll
            for (int p = 0; p < 2; p++)
                ldsm4(b_l[p], bL + (uint32_t)((brow + p * 16) * LDS + bcol) * 2);
            #pragma unroll
            for (int mt = 0; mt < 4; mt++)
                #pragma unroll
                for (int nt = 0; nt < 4; nt++)
                    mma_f32acc(acc[mt][nt], a_h[mt], b_l[nt >> 1][(nt & 1) * 2],
                               b_l[nt >> 1][(nt & 1) * 2 + 1]);
            uint32_t a_l[4][4];
            #pragma unroll
            for (int mt = 0; mt < 4; mt++) {
                int arow = wm * 64 + mt * 16 + (lane & 15);
                ldsm4(a_l[mt], aL + (uint32_t)(arow * LDS + acol) * 2);
            }
            #pragma unroll
            for (int mt = 0; mt < 4; mt++)
                #pragma unroll
                for (int nt = 0; nt < 4; nt++)
                    mma_f32acc(acc[mt][nt], a_l[mt], b_h[nt >> 1][(nt & 1) * 2],
                               b_h[nt >> 1][(nt & 1) * 2 + 1]);
        }
        if (k + 2 < nk)
            load4(sb + (uint32_t)((k + 2) % 3) * (4 * TB),
                  gA + (k + 2) * 64, gB + (k + 2) * 64, K, tid);
        CP_COMMIT();
    }
    #pragma unroll
    for (int mt = 0; mt < 4; mt++)
        #pragma unroll
        for (int nt = 0; nt < 4; nt++)
            #pragma unroll
            for (int r = 0; r < 4; r++) {
                int row = m0 + wm * 64 + mt * 16 + (lane >> 2) + (r >> 1) * 8;
                int col = n0 + wn * 32 + nt * 8 + (lane & 3) * 2 + (r & 1);
                float vv = acc[mt][nt][r];
                size_t o = (size_t)row * N + col;
                if (epi == 0) {
                    C[o] = vv;
                } else if (epi == 1) {
                    C[o] = vv + res[o];
                } else if (epi == 3) {
                    atomicAdd(&C[o], vv);
                } else {
                    vv = fmaxf(vv, 0.f); vv = vv * vv;
                    __half h, l;
                    split2h(vv, h, l);
                    size_t o2 = (size_t)row * 2 * N + col;
                    O2[o2] = h; O2[o2 + N] = l;
                }
            }
}

// ---------------- lm_head: fused 2-mma GEMM (Ah*(Bh+Bl)) + softcap/lse -------
__global__ void __launch_bounds__(256, 1)
lmhead_kernel(const __half* __restrict__ A, const __half* __restrict__ B,
              float* __restrict__ out, const int* __restrict__ targets, int store) {
    const int N = VOCAB, K = DMODEL;
    extern __shared__ __half smem[];
    const int tid = threadIdx.x, lane = tid & 31, wid = tid >> 5;
    const int wm = wid >> 2, wn = wid & 3;
    const int m0 = blockIdx.x * 128, n0 = blockIdx.y * 128;
    const uint32_t sb = (uint32_t)__cvta_generic_to_shared(smem);
    const __half* gA = A + (size_t)m0 * 2 * K;
    const __half* gB = B + (size_t)n0 * 2 * K;

    float acc[4][4][4];
    #pragma unroll
    for (int a = 0; a < 4; a++)
        #pragma unroll
        for (int b = 0; b < 4; b++)
            #pragma unroll
            for (int c = 0; c < 4; c++) acc[a][b][c] = 0.f;

    const int nk = K / 64;   // 12
    load3(sb, gA, gB, K, tid);
    CP_COMMIT();
    load3(sb + 3 * TB, gA + 64, gB + 64, K, tid);
    CP_COMMIT();

    for (int k = 0; k < nk; k++) {
        CP_WAIT1();
        __syncthreads();
        uint32_t st = sb + (uint32_t)(k % 3) * (3 * TB);
        uint32_t aH = st, bH = st + TB, bL = st + 2 * TB;
        #pragma unroll
        for (int kh = 0; kh < 4; kh++) {
            const int acol = kh * 16 + ((lane >> 4) << 3);
            const int bcol = kh * 16 + (((lane >> 3) & 1) << 3);
            const int brow = wn * 32 + ((lane >> 4) << 3) + (lane & 7);
            uint32_t a_h[4][4], b_h[2][4], b_l[2][4];
            #pragma unroll
            for (int mt = 0; mt < 4; mt++) {
                int arow = wm * 64 + mt * 16 + (lane & 15);
                ldsm4(a_h[mt], aH + (uint32_t)(arow * LDS + acol) * 2);
            }
            #pragma unroll
            for (int p = 0; p < 2; p++) {
                ldsm4(b_h[p], bH + (uint32_t)((brow + p * 16) * LDS + bcol) * 2);
                ldsm4(b_l[p], bL + (uint32_t)((brow + p * 16) * LDS + bcol) * 2);
            }
            #pragma unroll
            for (int mt = 0; mt < 4; mt++)
                #pragma unroll
                for (int nt = 0; nt < 4; nt++) {
                    mma_f32acc(acc[mt][nt], a_h[mt], b_h[nt >> 1][(nt & 1) * 2],
                               b_h[nt >> 1][(nt & 1) * 2 + 1]);
                    mma_f32acc(acc[mt][nt], a_h[mt], b_l[nt >> 1][(nt & 1) * 2],
                               b_l[nt >> 1][(nt & 1) * 2 + 1]);
                }
        }
        if (k + 2 < nk)
            load3(sb + (uint32_t)((k + 2) % 3) * (3 * TB),
                  gA + (k + 2) * 64, gB + (k + 2) * 64, K, tid);
        CP_COMMIT();
    }
    float ps[8];
    #pragma unroll
    for (int i = 0; i < 8; i++) ps[i] = 0.f;
    #pragma unroll
    for (int mt = 0; mt < 4; mt++)
        #pragma unroll
        for (int nt = 0; nt < 4; nt++)
            #pragma unroll
            for (int r = 0; r < 4; r++) {
                int row = m0 + wm * 64 + mt * 16 + (lane >> 2) + (r >> 1) * 8;
                int col = n0 + wn * 32 + nt * 8 + (lane & 3) * 2 + (r & 1);
                float vv = CAPV * tanhf(acc[mt][nt][r] * (1.f / CAPV));
                if (store)
                    out[(size_t)row * N + col] =
                        __bfloat162float(__float2bfloat16(vv));
                ps[mt * 2 + (r >> 1)] += __expf(vv - CAPV);
                if (col == targets[row]) g_tl[row] = vv;
            }
    #pragma unroll
    for (int i = 0; i < 8; i++) {
        ps[i] += __shfl_xor_sync(0xffffffffu, ps[i], 1);
        ps[i] += __shfl_xor_sync(0xffffffffu, ps[i], 2);
    }
    __syncthreads();
    float* red = (float*)smem;
    if ((lane & 3) == 0) {
        #pragma unroll
        for (int mt = 0; mt < 4; mt++)
            #pragma unroll
            for (int hh = 0; hh < 2; hh++) {
                int rl = wm * 64 + mt * 16 + (lane >> 2) + hh * 8;
                red[rl * 4 + wn] = ps[mt * 2 + hh];
            }
    }
    __syncthreads();
    if (tid < 128) {
        float s = red[tid * 4] + red[tid * 4 + 1] + red[tid * 4 + 2] + red[tid * 4 + 3];
        atomicAdd(&g_rowsum[m0 + tid], s);
    }
}

__global__ void zero_kernel() {
    for (int i = threadIdx.x; i < SEQ; i += blockDim.x) g_rowsum[i] = 0.f;
}

__global__ void loss_kernel(float* out_f) {
    float s = 0.f;
    for (int t = threadIdx.x; t < SEQ; t += blockDim.x)
        s += CAPV + logf(g_rowsum[t]) - g_tl[t];
    s = blockReduceSum(s);
    if (threadIdx.x == 0 && out_f) out_f[0] = s / (float)SEQ;
}

// ---------------- launch ------------------------------------------------------
extern "C" void kernel_launch(void* const* d_in, const int* in_sizes, int n_in,
                              void* d_out, int out_size) {
    const int*   idx     = (const int*)d_in[0];
    const int*   targets = (const int*)d_in[1];
    const float* emb     = (const float*)d_in[2];
    const float* ln1_w   = (const float*)d_in[3];
    const float* qkv_w   = (const float*)d_in[4];
    const float* q_norm  = (const float*)d_in[5];
    const float* k_norm  = (const float*)d_in[6];
    const float* proj_w  = (const float*)d_in[7];
    const float* ln2_w   = (const float*)d_in[8];
    const float* fc1_w   = (const float*)d_in[9];
    const float* fc2_w   = (const float*)d_in[10];
    const float* lnf_w   = (const float*)d_in[11];
    const float* lm_w    = (const float*)d_in[12];

    float *p_x, *p_big;
    cudaGetSymbolAddress((void**)&p_x, g_x);
    cudaGetSymbolAddress((void**)&p_big, g_big);
    __half *pqkv, *pproj, *pfc1, *pfc2, *plm, *pan2, *pah2;
    cudaGetSymbolAddress((void**)&pqkv, w2_qkv);
    cudaGetSymbolAddress((void**)&pproj, w2_proj);
    cudaGetSymbolAddress((void**)&pfc1, w2_fc1);
    cudaGetSymbolAddress((void**)&pfc2, w2_fc2);
    cudaGetSymbolAddress((void**)&plm, w2_lm);
    cudaGetSymbolAddress((void**)&pan2, an2);
    cudaGetSymbolAddress((void**)&pah2, ah2);

    cudaFuncSetAttribute(gemm2_kernel,
                         cudaFuncAttributeMaxDynamicSharedMemorySize, G4_SMEM);
    cudaFuncSetAttribute(lmhead_kernel,
                         cudaFuncAttributeMaxDynamicSharedMemorySize, G3_SMEM);
    cudaFuncSetAttribute(attn_kernel,
                         cudaFuncAttributeMaxDynamicSharedMemorySize, ATTN_SMEM);

    const long long NTV = (long long)SEQ * VOCAB;
    int store_logits = ((long long)out_size >= NTV) ? 1 : 0;

    split_all_kernel<<<8192, 256>>>((const float4*)qkv_w, (const float4*)proj_w,
                                    (const float4*)fc1_w, (const float4*)fc2_w,
                                    (const float4*)lm_w,
                                    pqkv, pproj, pfc1, pfc2, plm);
    embed_kernel<<<SEQ, 256>>>(idx, emb);

    for (int l = 0; l < LNUM; l++) {
        const float* l1 = ln1_w + (size_t)l * DMODEL;
        const float* qn = q_norm + (size_t)l * HDIM;
        const float* kn = k_norm + (size_t)l * HDIM;
        const float* l2 = ln2_w + (size_t)l * DMODEL;
        __half* qkw = pqkv + (size_t)l * 2304 * K2D;
        __half* pw  = pproj + (size_t)l * 768 * K2D;
        __half* f1  = pfc1 + (size_t)l * 3072 * K2D;
        __half* f2  = pfc2 + (size_t)l * 768 * K2F;

        rmsnorm_kernel<<<SEQ, 256>>>(p_x, l1);
        gemm2_kernel<<<dim3(SEQ / 128, 2304 / 128, 1), 256, G4_SMEM>>>(
            pan2, qkw, p_big, nullptr, nullptr, SEQ, 2304, DMODEL, 0, 1);
        if (l == 0) zero_kernel<<<1, 256>>>();
        {
            dim3 g(SEQ, NHEAD);
            rope_kernel<<<g, HDIM>>>(p_big, qn, kn);
        }
        {
            dim3 g(SEQ / 32, NHEAD);
            attn_kernel<<<g, 256, ATTN_SMEM>>>();
        }
        // proj: split-K=2, atomicAdd into residual x
        gemm2_kernel<<<dim3(SEQ / 128, DMODEL / 128, 2), 256, G4_SMEM>>>(
            pan2, pw, p_x, nullptr, nullptr, SEQ, DMODEL, DMODEL, 3, 2);
        rmsnorm_kernel<<<SEQ, 256>>>(p_x, l2);
        gemm2_kernel<<<dim3(SEQ / 128, FFDIM / 128, 1), 256, G4_SMEM>>>(
            pan2, f1, nullptr, nullptr, pah2, SEQ, FFDIM, DMODEL, 2, 1);
        // fc2: split-K=2, atomicAdd into residual x
        gemm2_kernel<<<dim3(SEQ / 128, DMODEL / 128, 2), 256, G4_SMEM>>>(
            pah2, f2, p_x, nullptr, nullptr, SEQ, DMODEL, FFDIM, 3, 2);
    }

    rmsnorm_kernel<<<SEQ, 256>>>(p_x, lnf_w);
    lmhead_kernel<<<dim3(SEQ / 128, VOCAB / 128), 256, G3_SMEM>>>(
        pan2, plm, (float*)d_out, targets, store_logits);
    if (store_logits) {
        float* lossp =
            ((long long)out_size > NTV) ? ((float*)d_out + NTV) : nullptr;
        loss_kernel<<<1, 256>>>(lossp);
    } else {
        loss_kernel<<<1, 256>>>((float*)d_out);
    }
}

// round 17
// speedup vs baseline: 1.1250x; 1.1250x over previous
#include <cuda_runtime.h>
#include <cuda_bf16.h>
#include <cuda_fp16.h>
#include <math.h>
#include <stdint.h>

// Model dims
#define LNUM 12
#define DMODEL 768
#define NHEAD 6
#define HDIM 128
#define FFDIM 3072
#define VOCAB 65536
#define SEQ 2048
#define EPSV 1e-5f
#define CAPV 30.0f

#define K3D (3 * DMODEL)    // 2304
#define K2D (2 * DMODEL)    // 1536 (lm_head 2-plane K)
#define K3F (3 * FFDIM)     // 9216

// GEMM tiling: 128x128 tile, BK=64, 3-stage cp.async, 2 CTAs/SM
#define LDS 72
#define SMEM_BYTES (3 * 128 * LDS * 2 * 2)   // 110592 B
// attention dynamic smem: Ktf[32][35] + Vtf[32][32] + sq4[64][32] (float4)
#define ATTN_SMEM ((32 * 35 + 32 * 32 + 64 * 32) * 16)   // 67072 B

// ---------------- scratch (static device arrays; no allocation) -------------
__device__ float g_x[SEQ * DMODEL];
__device__ float g_big[SEQ * K3D];
__device__ float g_q[SEQ * DMODEL];
__device__ float g_k[SEQ * DMODEL];
__device__ float g_v[SEQ * DMODEL];
__device__ float g_rowsum[SEQ];
__device__ float g_tl[SEQ];

// K-interleaved fp16 split planes: row n, cols [0,K)=hi,[K,2K)=lo,[2K,3K)=hi
__device__ __align__(16) __half w3_qkv[12LL * 2304 * K3D];
__device__ __align__(16) __half w3_proj[12LL * 768 * K3D];
__device__ __align__(16) __half w3_fc1[12LL * 3072 * K3D];
__device__ __align__(16) __half w3_fc2[12LL * 768 * K3F];
// lm_head: 2-plane [hi|lo], row stride K2D
__device__ __align__(16) __half w2_lm[65536LL * K2D];

// K-interleaved activation planes: row t, cols [0,K)=hi,[K,2K)=hi,[2K,3K)=lo
__device__ __align__(16) __half an3[SEQ * K3D];
__device__ __align__(16) __half ah3[SEQ * K3F];

// ---------------- helpers ----------------------------------------------------
__device__ __forceinline__ void split2h(float v, __half& h, __half& l) {
    h = __float2half_rn(v);
    l = __float2half_rn(v - __half2float(h));
}

__device__ __forceinline__ float blockReduceSum(float v) {
    __shared__ float sh[32];
    __syncthreads();
    int lane = threadIdx.x & 31, wid = threadIdx.x >> 5;
    #pragma unroll
    for (int o = 16; o; o >>= 1) v += __shfl_xor_sync(0xffffffffu, v, o);
    if (lane == 0) sh[wid] = v;
    __syncthreads();
    int nw = blockDim.x >> 5;
    v = (threadIdx.x < nw) ? sh[threadIdx.x] : 0.f;
    if (wid == 0) {
        #pragma unroll
        for (int o = 16; o; o >>= 1) v += __shfl_xor_sync(0xffffffffu, v, o);
        if (lane == 0) sh[0] = v;
    }
    __syncthreads();
    return sh[0];
}

__device__ __forceinline__ void ldsm4(uint32_t (&r)[4], uint32_t addr) {
    asm volatile("ldmatrix.sync.aligned.m8n8.x4.shared.b16 {%0,%1,%2,%3},[%4];"
                 : "=r"(r[0]), "=r"(r[1]), "=r"(r[2]), "=r"(r[3]) : "r"(addr));
}

__device__ __forceinline__ void mma_f32acc(float (&d)[4], const uint32_t (&a)[4],
                                           uint32_t b0, uint32_t b1) {
    asm volatile(
        "mma.sync.aligned.m16n8k16.row.col.f32.f16.f16.f32 "
        "{%0,%1,%2,%3},{%4,%5,%6,%7},{%8,%9},{%0,%1,%2,%3};"
        : "+f"(d[0]), "+f"(d[1]), "+f"(d[2]), "+f"(d[3])
        : "r"(a[0]), "r"(a[1]), "r"(a[2]), "r"(a[3]), "r"(b0), "r"(b1));
}

__device__ __forceinline__ void cp16(uint32_t dst, const void* src) {
    asm volatile("cp.async.cg.shared.global [%0], [%1], 16;" :: "r"(dst), "l"(src));
}
#define CP_COMMIT() asm volatile("cp.async.commit_group;")
#define CP_WAIT1() asm volatile("cp.async.wait_group 1;")

// load one 128x64 fp16 tile of A and B into a stage; separate row strides
__device__ __forceinline__ void load_stage(uint32_t sA, uint32_t sB,
                                           const __half* gA, const __half* gB,
                                           int ldA, int ldB, int tid) {
    int tRow = tid >> 3, tc = (tid & 7) * 8;
    #pragma unroll
    for (int p = 0; p < 4; p++) {
        int row = tRow + 32 * p;
        cp16(sA + (uint32_t)(row * LDS + tc) * 2, gA + (size_t)row * ldA + tc);
        cp16(sB + (uint32_t)(row * LDS + tc) * 2, gB + (size_t)row * ldB + tc);
    }
}

// ---------------- fused weight split: ONE launch -------------------------------
__device__ __forceinline__ void split_seg3(const float4* s, __half* d,
                                           unsigned n4, unsigned K,
                                           unsigned gid, unsigned gstride) {
    unsigned K4 = K >> 2;
    for (unsigned i = gid; i < n4; i += gstride) {
        float4 v = s[i];
        unsigned n = i / K4;
        unsigned k = (i - n * K4) << 2;
        __half* r = d + (size_t)n * 3 * K + k;
        float vv[4] = {v.x, v.y, v.z, v.w};
        #pragma unroll
        for (int j = 0; j < 4; j++) {
            __half h, l;
            split2h(vv[j], h, l);
            r[j] = h; r[K + j] = l; r[2 * K + j] = h;
        }
    }
}

__device__ __forceinline__ void split_seg2(const float4* s, __half* d,
                                           unsigned n4, unsigned K,
                                           unsigned gid, unsigned gstride) {
    unsigned K4 = K >> 2;
    for (unsigned i = gid; i < n4; i += gstride) {
        float4 v = s[i];
        unsigned n = i / K4;
        unsigned k = (i - n * K4) << 2;
        __half* r = d + (size_t)n * 2 * K + k;
        float vv[4] = {v.x, v.y, v.z, v.w};
        #pragma unroll
        for (int j = 0; j < 4; j++) {
            __half h, l;
            split2h(vv[j], h, l);
            r[j] = h; r[K + j] = l;
        }
    }
}

__global__ void split_all_kernel(const float4* qkv, const float4* proj,
                                 const float4* fc1, const float4* fc2,
                                 const float4* lm,
                                 __half* dqkv, __half* dproj,
                                 __half* dfc1, __half* dfc2, __half* dlm) {
    unsigned gid = blockIdx.x * blockDim.x + threadIdx.x;
    unsigned gs = gridDim.x * blockDim.x;
    split_seg3(qkv, dqkv, 12u * 2304 * 768 / 4, DMODEL, gid, gs);
    split_seg3(proj, dproj, 12u * 768 * 768 / 4, DMODEL, gid, gs);
    split_seg3(fc1, dfc1, 12u * 3072 * 768 / 4, DMODEL, gid, gs);
    split_seg3(fc2, dfc2, 12u * 768 * 3072 / 4, FFDIM, gid, gs);
    split_seg2(lm, dlm, 65536u * 768 / 4, DMODEL, gid, gs);
}

// ---------------- elementwise kernels ----------------------------------------
__global__ void embed_kernel(const int* __restrict__ idx,
                             const float* __restrict__ emb) {
    int t = blockIdx.x;
    int row = idx[t];
    const float* src = emb + (size_t)row * DMODEL;
    for (int i = threadIdx.x; i < DMODEL; i += blockDim.x)
        g_x[t * DMODEL + i] = src[i];
}

__global__ void rmsnorm_kernel(const float* __restrict__ x,
                               const float* __restrict__ w) {
    int t = blockIdx.x;
    const float* xr = x + (size_t)t * DMODEL;
    float s = 0.f;
    for (int i = threadIdx.x; i < DMODEL; i += blockDim.x) {
        float v = xr[i];
        s += v * v;
    }
    s = blockReduceSum(s);
    float r = rsqrtf(s / (float)DMODEL + EPSV);
    for (int i = threadIdx.x; i < DMODEL; i += blockDim.x) {
        float v = xr[i] * r * w[i];
        __half h, l;
        split2h(v, h, l);
        size_t o = (size_t)t * K3D + i;
        an3[o] = h; an3[o + DMODEL] = h; an3[o + 2 * DMODEL] = l;
    }
}

__global__ void rope_kernel(const float* __restrict__ qkv,
                            const float* __restrict__ qw,
                            const float* __restrict__ kw) {
    int t = blockIdx.x, h = blockIdx.y, d = threadIdx.x;
    const float* base = qkv + (size_t)t * K3D;
    float qd = base[h * HDIM + d];
    float kd = base[DMODEL + h * HDIM + d];
    float vd = base[2 * DMODEL + h * HDIM + d];
    float qs = blockReduceSum(qd * qd);
    float ks = blockReduceSum(kd * kd);
    float qn = qd * rsqrtf(qs / (float)HDIM + EPSV) * qw[d];
    float kn = kd * rsqrtf(ks / (float)HDIM + EPSV) * kw[d];
    __shared__ float sq[HDIM], sk[HDIM];
    sq[d] = qn; sk[d] = kn;
    __syncthreads();
    float expo = -(float)((d & 63) * 2) / (float)HDIM;
    float invf = expf(expo * logf(10000.f));
    float ang = (float)t * invf;
    float c = cosf(ang), s = sinf(ang);
    float qr = (d < 64) ? -sq[d + 64] : sq[d - 64];
    float kr = (d < 64) ? -sk[d + 64] : sk[d - 64];
    size_t oidx = (size_t)t * DMODEL + h * HDIM + d;
    g_q[oidx] = qn * c + qr * s;
    g_k[oidx] = kn * c + kr * s;
    g_v[oidx] = vd;
}

// ---------------- attention: 8 queries per warp, tile-wise online softmax ----
// Block = 8 warps x 8 queries = 64 queries. Lane = key within 32-key tile.
__global__ void __launch_bounds__(256) attn_kernel() {
    extern __shared__ float4 dyn[];
    float4 (*Ktf)[35] = (float4(*)[35])dyn;                       // [d4][key]
    float4 (*Vtf)[32] = (float4(*)[32])(dyn + 32 * 35);           // [key][d4]
    float4 (*sq4)[32] = (float4(*)[32])(dyn + 32 * 35 + 32 * 32); // [q][d4]
    const int h = blockIdx.y;
    const int qbase = blockIdx.x * 64;
    const int tid = threadIdx.x;
    const int warp = tid >> 5, lane = tid & 31;
    const int q0i = qbase + warp * 8;

    // load 64 queries x 128 dims
    #pragma unroll
    for (int it = 0; it < 8; it++) {
        int i = tid + it * 256;
        int r = i >> 5, c4 = i & 31;
        sq4[r][c4] = ((const float4*)(g_q + (size_t)(qbase + r) * DMODEL +
                                      h * HDIM))[c4];
    }

    float m[8], l[8];
    float4 acc[8];
    #pragma unroll
    for (int qq = 0; qq < 8; qq++) {
        m[qq] = -1e30f; l[qq] = 0.f;
        acc[qq] = make_float4(0.f, 0.f, 0.f, 0.f);
    }
    const int ntiles = (qbase >> 5) + 2;

    for (int tb = 0; tb < ntiles; tb++) {
        int kb = tb << 5;
        __syncthreads();
        #pragma unroll
        for (int it = 0; it < 4; it++) {
            int i = tid + it * 256;
            int r = i >> 5, c4 = i & 31;
            Ktf[c4][r] = ((const float4*)(g_k + (size_t)(kb + r) * DMODEL +
                                          h * HDIM))[c4];
            Vtf[r][c4] = ((const float4*)(g_v + (size_t)(kb + r) * DMODEL +
                                          h * HDIM))[c4];
        }
        __syncthreads();

        if (kb > q0i + 7) continue;   // warp-uniform: tile fully masked

        // scores for 8 queries; lane = key
        float s[8] = {0.f, 0.f, 0.f, 0.f, 0.f, 0.f, 0.f, 0.f};
        #pragma unroll
        for (int d4 = 0; d4 < 32; d4 += 4) {
            float4 k0 = Ktf[d4][lane],     k1 = Ktf[d4 + 1][lane];
            float4 k2 = Ktf[d4 + 2][lane], k3 = Ktf[d4 + 3][lane];
            #pragma unroll
            for (int qq = 0; qq < 8; qq++) {
                float4 q0 = sq4[warp * 8 + qq][d4];
                float4 q1 = sq4[warp * 8 + qq][d4 + 1];
                float4 q2 = sq4[warp * 8 + qq][d4 + 2];
                float4 q3 = sq4[warp * 8 + qq][d4 + 3];
                s[qq] += q0.x * k0.x + q0.y * k0.y + q0.z * k0.z + q0.w * k0.w
                       + q1.x * k1.x + q1.y * k1.y + q1.z * k1.z + q1.w * k1.w
                       + q2.x * k2.x + q2.y * k2.y + q2.z * k2.z + q2.w * k2.w
                       + q3.x * k3.x + q3.y * k3.y + q3.z * k3.z + q3.w * k3.w;
            }
        }
        // online softmax update per query
        float p8[8];
        #pragma unroll
        for (int qq = 0; qq < 8; qq++) {
            int jmax = q0i + qq - kb + 1;        // may be <= 0 for last tile
            float sv = s[qq] * 0.08838834764831845f;
            if (lane >= jmax) sv = -1e30f;
            float mt = sv;
            #pragma unroll
            for (int o = 16; o; o >>= 1)
                mt = fmaxf(mt, __shfl_xor_sync(0xffffffffu, mt, o));
            float mn = fmaxf(m[qq], mt);
            float corr = __expf(m[qq] - mn);
            float p = __expf(sv - mn);
            float psum = p;
            #pragma unroll
            for (int o = 16; o; o >>= 1)
                psum += __shfl_xor_sync(0xffffffffu, psum, o);
            l[qq] = l[qq] * corr + psum;
            m[qq] = mn;
            acc[qq].x *= corr; acc[qq].y *= corr;
            acc[qq].z *= corr; acc[qq].w *= corr;
            p8[qq] = p;
        }
        // PV: V vector loaded once, used for 8 queries
        #pragma unroll
        for (int j = 0; j < 32; j++) {
            float4 vv = Vtf[j][lane];
            #pragma unroll
            for (int qq = 0; qq < 8; qq++) {
                float pj = __shfl_sync(0xffffffffu, p8[qq], j);
                acc[qq].x += pj * vv.x; acc[qq].y += pj * vv.y;
                acc[qq].z += pj * vv.z; acc[qq].w += pj * vv.w;
            }
        }
    }
    #pragma unroll
    for (int qq = 0; qq < 8; qq++) {
        float inv = 1.f / l[qq];
        float ov[4] = {acc[qq].x * inv, acc[qq].y * inv,
                       acc[qq].z * inv, acc[qq].w * inv};
        #pragma unroll
        for (int q = 0; q < 4; q++) {
            int i = h * HDIM + lane * 4 + q;
            __half hh, ll;
            split2h(ov[q], hh, ll);
            size_t o = (size_t)(q0i + qq) * K3D + i;
            an3[o] = hh; an3[o + DMODEL] = hh; an3[o + 2 * DMODEL] = ll;
        }
    }
}

// ---------------- pipelined fp16 GEMM 128x128: C = A * B^T --------------------
// epi: 0 = f32 store, 1 = +res f32 store, 2 = relu^2 -> triple fp16 O3,
//      3 = atomicAdd into C (split-K partial; blockIdx.z selects K chunk)
__global__ void __launch_bounds__(256, 2)
gemm_kernel(const __half* __restrict__ A, const __half* __restrict__ B,
            float* __restrict__ C, const float* __restrict__ res,
            __half* __restrict__ O3,
            int M, int N, int Kp, int epi, int ksplit) {
    extern __shared__ __half smem[];
    __half* sA = smem;
    __half* sB = smem + 3 * 128 * LDS;
    const int tid = threadIdx.x, lane = tid & 31, wid = tid >> 5;
    const int wm = wid >> 2, wn = wid & 3;
    const int m0 = blockIdx.x * 128, n0 = blockIdx.y * 128;
    const uint32_t sAu = (uint32_t)__cvta_generic_to_shared(sA);
    const uint32_t sBu = (uint32_t)__cvta_generic_to_shared(sB);
    const uint32_t stageB = 128 * LDS * 2;
    const int nk = Kp / 64 / ksplit;
    const int koff = blockIdx.z * nk * 64;
    const __half* gA = A + (size_t)m0 * Kp + koff;
    const __half* gB = B + (size_t)n0 * Kp + koff;

    float acc[4][4][4];
    #pragma unroll
    for (int a = 0; a < 4; a++)
        #pragma unroll
        for (int b = 0; b < 4; b++)
            #pragma unroll
            for (int c = 0; c < 4; c++) acc[a][b][c] = 0.f;

    load_stage(sAu, sBu, gA, gB, Kp, Kp, tid);
    CP_COMMIT();
    load_stage(sAu + stageB, sBu + stageB, gA + 64, gB + 64, Kp, Kp, tid);
    CP_COMMIT();

    for (int k = 0; k < nk; k++) {
        CP_WAIT1();
        __syncthreads();
        int st = k % 3;
        uint32_t aB = sAu + st * stageB;
        uint32_t bB = sBu + st * stageB;
        #pragma unroll
        for (int kh = 0; kh < 4; kh++) {
            uint32_t a[4][4], b[2][4];
            const int acol = kh * 16 + ((lane >> 4) << 3);
            #pragma unroll
            for (int mt = 0; mt < 4; mt++) {
                int arow = wm * 64 + mt * 16 + (lane & 15);
                ldsm4(a[mt], aB + (uint32_t)(arow * LDS + acol) * 2);
            }
            const int brow = wn * 32 + ((lane >> 4) << 3) + (lane & 7);
            const int bcol = kh * 16 + (((lane >> 3) & 1) << 3);
            #pragma unroll
            for (int p = 0; p < 2; p++)
                ldsm4(b[p], bB + (uint32_t)((brow + p * 16) * LDS + bcol) * 2);
            #pragma unroll
            for (int mt = 0; mt < 4; mt++)
                #pragma unroll
                for (int nt = 0; nt < 4; nt++)
                    mma_f32acc(acc[mt][nt], a[mt], b[nt >> 1][(nt & 1) * 2],
                               b[nt >> 1][(nt & 1) * 2 + 1]);
        }
        if (k + 2 < nk) {
            int s2 = (k + 2) % 3;
            load_stage(sAu + s2 * stageB, sBu + s2 * stageB,
                       gA + (size_t)(k + 2) * 64, gB + (size_t)(k + 2) * 64,
                       Kp, Kp, tid);
        }
        CP_COMMIT();
    }
    #pragma unroll
    for (int mt = 0; mt < 4; mt++)
        #pragma unroll
        for (int nt = 0; nt < 4; nt++)
            #pragma unroll
            for (int r = 0; r < 4; r++) {
                int row = m0 + wm * 64 + mt * 16 + (lane >> 2) + (r >> 1) * 8;
                int col = n0 + wn * 32 + nt * 8 + (lane & 3) * 2 + (r & 1);
                float vv = acc[mt][nt][r];
                size_t o = (size_t)row * N + col;
                if (epi == 0) {
                    C[o] = vv;
                } else if (epi == 1) {
                    C[o] = vv + res[o];
                } else if (epi == 3) {
                    atomicAdd(&C[o], vv);
                } else {
                    vv = fmaxf(vv, 0.f); vv = vv * vv;
                    __half h, l;
                    split2h(vv, h, l);
                    size_t o3 = (size_t)row * 3 * N + col;
                    O3[o3] = h; O3[o3 + N] = h; O3[o3 + 2 * N] = l;
                }
            }
}

// ---------------- lm_head: 2-plane GEMM (A stride K3D, Kp=K2D) ---------------
__global__ void __launch_bounds__(256, 2)
lmhead_kernel(const __half* __restrict__ A, const __half* __restrict__ B,
              float* __restrict__ out, const int* __restrict__ targets, int store) {
    const int N = VOCAB, Kp = K2D, ldA = K3D;
    extern __shared__ __half smem[];
    __half* sA = smem;
    __half* sB = smem + 3 * 128 * LDS;
    const int tid = threadIdx.x, lane = tid & 31, wid = tid >> 5;
    const int wm = wid >> 2, wn = wid & 3;
    const int m0 = blockIdx.x * 128, n0 = blockIdx.y * 128;
    const uint32_t sAu = (uint32_t)__cvta_generic_to_shared(sA);
    const uint32_t sBu = (uint32_t)__cvta_generic_to_shared(sB);
    const uint32_t stageB = 128 * LDS * 2;
    const __half* gA = A + (size_t)m0 * ldA;
    const __half* gB = B + (size_t)n0 * Kp;

    float acc[4][4][4];
    #pragma unroll
    for (int a = 0; a < 4; a++)
        #pragma unroll
        for (int b = 0; b < 4; b++)
            #pragma unroll
            for (int c = 0; c < 4; c++) acc[a][b][c] = 0.f;

    const int nk = Kp / 64;   // 24
    load_stage(sAu, sBu, gA, gB, ldA, Kp, tid);
    CP_COMMIT();
    load_stage(sAu + stageB, sBu + stageB, gA + 64, gB + 64, ldA, Kp, tid);
    CP_COMMIT();

    for (int k = 0; k < nk; k++) {
        CP_WAIT1();
        __syncthreads();
        int st = k % 3;
        uint32_t aB = sAu + st * stageB;
        uint32_t bB = sBu + st * stageB;
        #pragma unroll
        for (int kh = 0; kh < 4; kh++) {
            uint32_t a[4][4], b[2][4];
            const int acol = kh * 16 + ((lane >> 4) << 3);
            #pragma unroll
            for (int mt = 0; mt < 4; mt++) {
                int arow = wm * 64 + mt * 16 + (lane & 15);
                ldsm4(a[mt], aB + (uint32_t)(arow * LDS + acol) * 2);
            }
            const int brow = wn * 32 + ((lane >> 4) << 3) + (lane & 7);
            const int bcol = kh * 16 + (((lane >> 3) & 1) << 3);
            #pragma unroll
            for (int p = 0; p < 2; p++)
                ldsm4(b[p], bB + (uint32_t)((brow + p * 16) * LDS + bcol) * 2);
            #pragma unroll
            for (int mt = 0; mt < 4; mt++)
                #pragma unroll
                for (int nt = 0; nt < 4; nt++)
                    mma_f32acc(acc[mt][nt], a[mt], b[nt >> 1][(nt & 1) * 2],
                               b[nt >> 1][(nt & 1) * 2 + 1]);
        }
        if (k + 2 < nk) {
            int s2 = (k + 2) % 3;
            load_stage(sAu + s2 * stageB, sBu + s2 * stageB,
                       gA + (size_t)(k + 2) * 64, gB + (size_t)(k + 2) * 64,
                       ldA, Kp, tid);
        }
        CP_COMMIT();
    }
    float ps[8];
    #pragma unroll
    for (int i = 0; i < 8; i++) ps[i] = 0.f;
    #pragma unroll
    for (int mt = 0; mt < 4; mt++)
        #pragma unroll
        for (int nt = 0; nt < 4; nt++)
            #pragma unroll
            for (int r = 0; r < 4; r++) {
                int row = m0 + wm * 64 + mt * 16 + (lane >> 2) + (r >> 1) * 8;
                int col = n0 + wn * 32 + nt * 8 + (lane & 3) * 2 + (r & 1);
                float vv = CAPV * tanhf(acc[mt][nt][r] * (1.f / CAPV));
                if (store)
                    out[(size_t)row * N + col] =
                        __bfloat162float(__float2bfloat16(vv));
                ps[mt * 2 + (r >> 1)] += __expf(vv - CAPV);
                if (col == targets[row]) g_tl[row] = vv;
            }
    #pragma unroll
    for (int i = 0; i < 8; i++) {
        ps[i] += __shfl_xor_sync(0xffffffffu, ps[i], 1);
        ps[i] += __shfl_xor_sync(0xffffffffu, ps[i], 2);
    }
    __syncthreads();
    float* red = (float*)smem;
    if ((lane & 3) == 0) {
        #pragma unroll
        for (int mt = 0; mt < 4; mt++)
            #pragma unroll
            for (int hh = 0; hh < 2; hh++) {
                int rl = wm * 64 + mt * 16 + (lane >> 2) + hh * 8;
                red[rl * 4 + wn] = ps[mt * 2 + hh];
            }
    }
    __syncthreads();
    if (tid < 128) {
        float s = red[tid * 4] + red[tid * 4 + 1] + red[tid * 4 + 2] + red[tid * 4 + 3];
        atomicAdd(&g_rowsum[m0 + tid], s);
    }
}

__global__ void zero_kernel() {
    for (int i = threadIdx.x; i < SEQ; i += blockDim.x) g_rowsum[i] = 0.f;
}

__global__ void loss_kernel(float* out_f) {
    float s = 0.f;
    for (int t = threadIdx.x; t < SEQ; t += blockDim.x)
        s += CAPV + logf(g_rowsum[t]) - g_tl[t];
    s = blockReduceSum(s);
    if (threadIdx.x == 0 && out_f) out_f[0] = s / (float)SEQ;
}

// ---------------- launch ------------------------------------------------------
extern "C" void kernel_launch(void* const* d_in, const int* in_sizes, int n_in,
                              void* d_out, int out_size) {
    const int*   idx     = (const int*)d_in[0];
    const int*   targets = (const int*)d_in[1];
    const float* emb     = (const float*)d_in[2];
    const float* ln1_w   = (const float*)d_in[3];
    const float* qkv_w   = (const float*)d_in[4];
    const float* q_norm  = (const float*)d_in[5];
    const float* k_norm  = (const float*)d_in[6];
    const float* proj_w  = (const float*)d_in[7];
    const float* ln2_w   = (const float*)d_in[8];
    const float* fc1_w   = (const float*)d_in[9];
    const float* fc2_w   = (const float*)d_in[10];
    const float* lnf_w   = (const float*)d_in[11];
    const float* lm_w    = (const float*)d_in[12];

    float *p_x, *p_big;
    cudaGetSymbolAddress((void**)&p_x, g_x);
    cudaGetSymbolAddress((void**)&p_big, g_big);
    __half *pqkv, *pproj, *pfc1, *pfc2, *plm, *pan3, *pah3;
    cudaGetSymbolAddress((void**)&pqkv, w3_qkv);
    cudaGetSymbolAddress((void**)&pproj, w3_proj);
    cudaGetSymbolAddress((void**)&pfc1, w3_fc1);
    cudaGetSymbolAddress((void**)&pfc2, w3_fc2);
    cudaGetSymbolAddress((void**)&plm, w2_lm);
    cudaGetSymbolAddress((void**)&pan3, an3);
    cudaGetSymbolAddress((void**)&pah3, ah3);

    cudaFuncSetAttribute(gemm_kernel,
                         cudaFuncAttributeMaxDynamicSharedMemorySize, SMEM_BYTES);
    cudaFuncSetAttribute(lmhead_kernel,
                         cudaFuncAttributeMaxDynamicSharedMemorySize, SMEM_BYTES);
    cudaFuncSetAttribute(attn_kernel,
                         cudaFuncAttributeMaxDynamicSharedMemorySize, ATTN_SMEM);

    const long long NTV = (long long)SEQ * VOCAB;
    int store_logits = ((long long)out_size >= NTV) ? 1 : 0;

    split_all_kernel<<<8192, 256>>>((const float4*)qkv_w, (const float4*)proj_w,
                                    (const float4*)fc1_w, (const float4*)fc2_w,
                                    (const float4*)lm_w,
                                    pqkv, pproj, pfc1, pfc2, plm);
    embed_kernel<<<SEQ, 256>>>(idx, emb);

    for (int l = 0; l < LNUM; l++) {
        const float* l1 = ln1_w + (size_t)l * DMODEL;
        const float* qn = q_norm + (size_t)l * HDIM;
        const float* kn = k_norm + (size_t)l * HDIM;
        const float* l2 = ln2_w + (size_t)l * DMODEL;
        __half* qkw = pqkv + (size_t)l * 2304 * K3D;
        __half* pw  = pproj + (size_t)l * 768 * K3D;
        __half* f1  = pfc1 + (size_t)l * 3072 * K3D;
        __half* f2  = pfc2 + (size_t)l * 768 * K3F;

        rmsnorm_kernel<<<SEQ, 256>>>(p_x, l1);
        gemm_kernel<<<dim3(SEQ / 128, 2304 / 128, 1), 256, SMEM_BYTES>>>(
            pan3, qkw, p_big, nullptr, nullptr, SEQ, 2304, K3D, 0, 1);
        if (l == 0) zero_kernel<<<1, 256>>>();
        {
            dim3 g(SEQ, NHEAD);
            rope_kernel<<<g, HDIM>>>(p_big, qn, kn);
        }
        {
            dim3 g(SEQ / 64, NHEAD);
            attn_kernel<<<g, 256, ATTN_SMEM>>>();
        }
        // proj: split-K=2, full 128x128 tiles, atomicAdd into residual x
        gemm_kernel<<<dim3(SEQ / 128, DMODEL / 128, 2), 256, SMEM_BYTES>>>(
            pan3, pw, p_x, nullptr, nullptr, SEQ, DMODEL, K3D, 3, 2);
        rmsnorm_kernel<<<SEQ, 256>>>(p_x, l2);
        gemm_kernel<<<dim3(SEQ / 128, FFDIM / 128, 1), 256, SMEM_BYTES>>>(
            pan3, f1, nullptr, nullptr, pah3, SEQ, FFDIM, K3D, 2, 1);
        // fc2: split-K=2, atomicAdd into residual x
        gemm_kernel<<<dim3(SEQ / 128, DMODEL / 128, 2), 256, SMEM_BYTES>>>(
            pah3, f2, p_x, nullptr, nullptr, SEQ, DMODEL, K3F, 3, 2);
    }

    rmsnorm_kernel<<<SEQ, 256>>>(p_x, lnf_w);
    lmhead_kernel<<<dim3(SEQ / 128, VOCAB / 128), 256, SMEM_BYTES>>>(
        pan3, plm, (float*)d_out, targets, store_logits);
    if (store_logits) {
        float* lossp =
            ((long long)out_size > NTV) ? ((float*)d_out + NTV) : nullptr;
        loss_kernel<<<1, 256>>>(lossp);
    } else {
        loss_kernel<<<1, 256>>>((float*)d_out);
    }
}